// round 8
// baseline (speedup 1.0000x reference)
#include <cuda_runtime.h>
#include <cuda_bf16.h>
#include <math.h>
#include <stdint.h>

#define BSZ 4
#define LSEQ 2048
#define DM 1024
#define DI 2048
#define NS 16
#define RK 64
#define E2 96
#define OUT_MAIN (BSZ*LSEQ*DM)

__device__ float g_x[(size_t)BSZ*DI*LSEQ];
__device__ float g_z[(size_t)BSZ*DI*LSEQ];
__device__ float g_xc[(size_t)BSZ*DI*LSEQ];
__device__ float g_delta[(size_t)BSZ*DI*LSEQ];
__device__ float g_xdbl[(size_t)BSZ*LSEQ*E2];
__device__ float g_feat[32*DI];
__device__ float g_A[DI*NS];
__device__ float g_alphaF[DI];
__device__ float g_att[DI];
__device__ float g_colmax[NS], g_colmin[NS], g_attmax[1];
__device__ float g_cw[9*16], g_sw[9*16], g_ch[16*16], g_sh[16*16], g_mask[16*9];

__device__ __nv_bfloat16 w_ip_h[(size_t)2*DI*DM], w_ip_l[(size_t)2*DI*DM];
__device__ __nv_bfloat16 w_xp_h[E2*DI], w_xp_l[E2*DI];
__device__ __nv_bfloat16 w_dt_h[DI*RK], w_dt_l[DI*RK];
__device__ __nv_bfloat16 w_op_h[(size_t)DM*DI], w_op_l[(size_t)DM*DI];
__device__ __nv_bfloat16 hs_h[(size_t)BSZ*LSEQ*DM], hs_l[(size_t)BSZ*LSEQ*DM];
__device__ __nv_bfloat16 xcT_h[(size_t)BSZ*LSEQ*DI], xcT_l[(size_t)BSZ*LSEQ*DI];
__device__ __nv_bfloat16 xdbl_h[(size_t)BSZ*LSEQ*E2], xdbl_l[(size_t)BSZ*LSEQ*E2];
__device__ __nv_bfloat16 yg_h[(size_t)BSZ*LSEQ*DI], yg_l[(size_t)BSZ*LSEQ*DI];

__device__ __forceinline__ uint32_t smem_u32(const void* p) {
    uint32_t a;
    asm("{ .reg .u64 t; cvta.to.shared.u64 t, %1; cvt.u32.u64 %0, t; }" : "=r"(a) : "l"(p));
    return a;
}
__device__ __forceinline__ void bsplit(float x, __nv_bfloat16& h, __nv_bfloat16& l) {
    h = __float2bfloat16(x);
    l = __float2bfloat16(x - __bfloat162float(h));
}
#define LDM4(r, addr) \
    asm volatile("ldmatrix.sync.aligned.m8n8.x4.shared.b16 {%0,%1,%2,%3}, [%4];" \
        : "=r"((r)[0]), "=r"((r)[1]), "=r"((r)[2]), "=r"((r)[3]) : "r"(addr))
#define MMA(c, a, b0v, b1v) \
    asm volatile("mma.sync.aligned.m16n8k16.row.col.f32.bf16.bf16.f32 " \
        "{%0,%1,%2,%3}, {%4,%5,%6,%7}, {%8,%9}, {%0,%1,%2,%3};" \
        : "+f"((c)[0]), "+f"((c)[1]), "+f"((c)[2]), "+f"((c)[3]) \
        : "r"((a)[0]), "r"((a)[1]), "r"((a)[2]), "r"((a)[3]), "r"(b0v), "r"(b1v))
#define CP16(s, g) asm volatile("cp.async.cg.shared.global [%0], [%1], 16;" :: "r"(s), "l"(g))
#define CP_COMMIT() asm volatile("cp.async.commit_group;" ::: "memory")
#define CP_WAIT2()  asm volatile("cp.async.wait_group 2;" ::: "memory")

__global__ void init_tables_kernel() {
    int tid = threadIdx.x;
    if (tid < 144) {
        int kw = tid/16, w = tid%16;
        float a = (float)(w*kw)/8.0f;
        g_cw[kw*16+w] = cospif(a); g_sw[kw*16+w] = sinpif(a);
    }
    { int kh = tid/16, h = tid%16;
      float a = (float)(h*kh)/8.0f;
      g_ch[kh*16+h] = cospif(a); g_sh[kh*16+h] = sinpif(a); }
    if (tid < 144) {
        int kh = tid/9, kw = tid%9;
        int i = (kh+8)&15, j = (kw+4)%9;
        float hh = (i-8)/16.0f, ww = (j-4)/9.0f;
        g_mask[tid] = (sqrtf(hh*hh+ww*ww) >= 0.5f) ? 1.0f : 0.0f;
    }
}

__global__ __launch_bounds__(256)
void split_kernel(const float* __restrict__ s, __nv_bfloat16* __restrict__ hp,
                  __nv_bfloat16* __restrict__ lp, int n4) {
    int i = blockIdx.x*256 + threadIdx.x;
    if (i >= n4) return;
    float4 v = *(const float4*)(s + (size_t)i*4);
    __nv_bfloat16 h0,l0,h1,l1,h2,l2,h3,l3;
    bsplit(v.x,h0,l0); bsplit(v.y,h1,l1); bsplit(v.z,h2,l2); bsplit(v.w,h3,l3);
    __nv_bfloat162 hv0 = {h0,h1}, hv1 = {h2,h3}, lv0 = {l0,l1}, lv1 = {l2,l3};
    uint2 hu, lu;
    hu.x = *(uint32_t*)&hv0; hu.y = *(uint32_t*)&hv1;
    lu.x = *(uint32_t*)&lv0; lu.y = *(uint32_t*)&lv1;
    *(uint2*)(hp + (size_t)i*4) = hu;
    *(uint2*)(lp + (size_t)i*4) = lu;
}

// ---- 3-stage cp.async bf16x3 GEMM: D[m][n] = sum_k W[m][k]*X[n][k] ----
#define STG 40960
#define PL_AH 0
#define PL_AL 10240
#define PL_BH 20480
#define PL_BL 30720
#define GSMEM (3*STG)

template<int MODE>
__global__ __launch_bounds__(256)
void gemm_mma_kernel(const float* __restrict__ bias, float* __restrict__ Out)
{
    extern __shared__ char sm[];
    const __nv_bfloat16 *Wh, *Wl, *Xh, *Xl;
    int ldw, ldx, K, wmax;
    if (MODE==0) { Wh=w_ip_h; Wl=w_ip_l; Xh=hs_h;   Xl=hs_l;   ldw=DM; ldx=DM; K=DM; wmax=2*DI-1; }
    else if (MODE==1) { Wh=w_xp_h; Wl=w_xp_l; Xh=xcT_h; Xl=xcT_l; ldw=DI; ldx=DI; K=DI; wmax=E2-1; }
    else if (MODE==2) { Wh=w_dt_h; Wl=w_dt_l; Xh=xdbl_h; Xl=xdbl_l; ldw=RK; ldx=E2; K=RK; wmax=DI-1; }
    else { Wh=w_op_h; Wl=w_op_l; Xh=yg_h; Xl=yg_l; ldw=DI; ldx=DI; K=DI; wmax=DM-1; }

    int tid = threadIdx.x, wid = tid>>5, lane = tid&31;
    int wm = wid & 1, wn = wid >> 1;
    int i0 = blockIdx.y*128, j0 = blockIdx.x*128;
    uint32_t sb = smem_u32(sm);
    int frow = ((lane>>3)&1)*8 + (lane&7);
    uint32_t khalf = (uint32_t)(lane>>4)*16;
    uint32_t aOff = (uint32_t)(wm*64 + frow)*80 + khalf;
    uint32_t bOff = (uint32_t)(wn*32 + frow)*80 + khalf;

    float acc[4][4][4];
#pragma unroll
    for (int a=0;a<4;a++)
#pragma unroll
        for (int b=0;b<4;b++)
#pragma unroll
            for (int q=0;q<4;q++) acc[a][b][q]=0.f;

    int NC = K/32;

    auto issue = [&](int c) {
        if (c >= NC) return;
        int s = c % 3, k0 = c*32;
        uint32_t base = sb + (uint32_t)s*STG;
#pragma unroll
        for (int it=0; it<2; it++) {
            int idx = tid + it*256;
            int r = idx>>2, u = idx&3;
            uint32_t so = (uint32_t)r*80 + (uint32_t)u*16;
            int wr = i0 + r; if (wr > wmax) wr = wmax;
            size_t wo = (size_t)wr*ldw + k0 + u*8;
            size_t xo = (size_t)(j0+r)*ldx + k0 + u*8;
            CP16(base+PL_AH+so, Wh+wo);
            CP16(base+PL_AL+so, Wl+wo);
            CP16(base+PL_BH+so, Xh+xo);
            CP16(base+PL_BL+so, Xl+xo);
        }
    };

    issue(0); CP_COMMIT();
    issue(1); CP_COMMIT();
    issue(2); CP_COMMIT();
    CP_WAIT2();
    __syncthreads();

    for (int c = 0; c < NC; c++) {
        uint32_t st = sb + (uint32_t)(c%3)*STG;
#pragma unroll
        for (int kk = 0; kk < 2; kk++) {
            uint32_t ko = (uint32_t)kk*32;
            uint32_t ah[4][4], al[4][4];
#pragma unroll
            for (int mi=0; mi<4; mi++) {
                LDM4(ah[mi], st+PL_AH+aOff+(uint32_t)mi*1280+ko);
                LDM4(al[mi], st+PL_AL+aOff+(uint32_t)mi*1280+ko);
            }
#pragma unroll
            for (int j=0; j<2; j++) {
                uint32_t bh[4], bl[4];
                LDM4(bh, st+PL_BH+bOff+(uint32_t)j*1280+ko);
                LDM4(bl, st+PL_BL+bOff+(uint32_t)j*1280+ko);
#pragma unroll
                for (int mi=0; mi<4; mi++) {
#pragma unroll
                    for (int nt=0; nt<2; nt++) {
                        float* cc = acc[mi][j*2+nt];
                        MMA(cc, ah[mi], bh[nt], bh[nt+2]);
                        MMA(cc, ah[mi], bl[nt], bl[nt+2]);
                        MMA(cc, al[mi], bh[nt], bh[nt+2]);
                    }
                }
            }
        }
        __syncthreads();
        issue(c+3);
        CP_COMMIT();
        CP_WAIT2();
        __syncthreads();
    }

#pragma unroll
    for (int mi=0; mi<4; mi++) {
        int mBase = i0 + wm*64 + mi*16 + (lane>>2);
#pragma unroll
        for (int ni=0; ni<4; ni++) {
            int n0 = j0 + wn*32 + ni*8 + (lane&3)*2;
            float* c = acc[mi][ni];
#pragma unroll
            for (int rr=0; rr<2; rr++) {
                int m = mBase + rr*8;
                float v0 = c[rr*2], v1 = c[rr*2+1];
                if (MODE==0) {
                    int b_ = n0>>11, l_ = n0&2047;
                    float* dst = (m < DI) ? (g_x + ((size_t)(b_*DI+m))*LSEQ + l_)
                                          : (g_z + ((size_t)(b_*DI+m-DI))*LSEQ + l_);
                    float2 o; o.x=v0; o.y=v1;
                    *(float2*)dst = o;
                } else if (MODE==1) {
                    if (m < RK) {
                        __nv_bfloat16 h0,l0,h1,l1;
                        bsplit(v0,h0,l0); bsplit(v1,h1,l1);
                        xdbl_h[(size_t)n0*E2+m] = h0; xdbl_l[(size_t)n0*E2+m] = l0;
                        xdbl_h[(size_t)(n0+1)*E2+m] = h1; xdbl_l[(size_t)(n0+1)*E2+m] = l1;
                    } else if (m < E2) {
                        g_xdbl[(size_t)n0*E2 + m] = v0;
                        g_xdbl[(size_t)(n0+1)*E2 + m] = v1;
                    }
                } else if (MODE==2) {
                    int b_ = n0>>11, l_ = n0&2047;
                    float bi = bias[m];
                    float s0 = v0 + bi, s1 = v1 + bi;
                    s0 = (s0 > 20.0f) ? s0 : log1pf(__expf(s0));
                    s1 = (s1 > 20.0f) ? s1 : log1pf(__expf(s1));
                    float2 o; o.x=s0; o.y=s1;
                    *(float2*)(g_delta + ((size_t)(b_*DI+m))*LSEQ + l_) = o;
                } else {
                    Out[(size_t)n0*DM + m]     = v0;
                    Out[(size_t)(n0+1)*DM + m] = v1;
                }
            }
        }
    }
}

// ---- fused conv(4)+SiLU + transpose + split ----
__global__ __launch_bounds__(256)
void conv_tr_kernel(const float* __restrict__ cw, const float* __restrict__ cb) {
    __shared__ float tile[32][36];
    __shared__ float t2[32][33];
    __shared__ float cwS[32][4];
    __shared__ float cbS[32];
    int b = blockIdx.z;
    int l0 = blockIdx.x*32, d0 = blockIdx.y*32;
    int tx = threadIdx.x & 31, ty = threadIdx.x >> 5;
    int tid = threadIdx.x;

    if (tid < 128) cwS[tid>>2][tid&3] = cw[(d0 + (tid>>2))*4 + (tid&3)];
    else if (tid < 160) cbS[tid-128] = cb[d0 + tid - 128];
#pragma unroll
    for (int q = 0; q < 5; q++) {
        int idx = tid + q*256;
        if (idx < 32*36) {
            int r = idx / 36, cc = idx % 36;
            int l = l0 - 4 + cc;
            tile[r][cc] = (l >= 0) ? g_x[((size_t)(b*DI + d0 + r))*LSEQ + l] : 0.0f;
        }
    }
    __syncthreads();
#pragma unroll
    for (int j = 0; j < 32; j += 8) {
        int r = ty + j;
        float acc = cbS[r];
#pragma unroll
        for (int k = 0; k < 4; k++) acc = fmaf(tile[r][tx+1+k], cwS[r][k], acc);
        float sg = 1.0f/(1.0f+__expf(-acc));
        float v = acc*sg;
        g_xc[((size_t)(b*DI + d0 + r))*LSEQ + l0 + tx] = v;
        t2[r][tx] = v;
    }
    __syncthreads();
    size_t dbase = (size_t)b*LSEQ*DI;
#pragma unroll
    for (int j = 0; j < 32; j += 8) {
        float v = t2[tx][ty+j];
        __nv_bfloat16 h, l;
        bsplit(v, h, l);
        size_t o = dbase + (size_t)(l0+ty+j)*DI + d0+tx;
        xcT_h[o] = h; xcT_l[o] = l;
    }
}

// ---- fft features ----
__global__ __launch_bounds__(256)
void fft_feat_kernel() {
    __shared__ float xp[256], Yr[144], Yi[144], sA[256], sH[256];
    int bid = blockIdx.x;
    int f = bid>>11, c = bid&2047;
    int b = f>>3, t = f&7;
    int tid = threadIdx.x;
    xp[tid] = g_x[((size_t)(b*DI+c))*LSEQ + t*256 + tid];
    __syncthreads();
    if (tid < 144) {
        int h = tid/9, kw = tid%9;
        float yr = 0.f, yi = 0.f;
#pragma unroll
        for (int w = 0; w < 16; w++) {
            float v = xp[h*16+w];
            yr += v*g_cw[kw*16+w]; yi -= v*g_sw[kw*16+w];
        }
        Yr[tid] = yr; Yi[tid] = yi;
    }
    __syncthreads();
    float a = 0.f, hi = 0.f;
    if (tid < 144) {
        int kh = tid/9, kw = tid%9;
        float zr = 0.f, zi = 0.f;
#pragma unroll
        for (int h = 0; h < 16; h++) {
            float cc = g_ch[kh*16+h], ss = g_sh[kh*16+h];
            float yr = Yr[h*9+kw], yi = Yi[h*9+kw];
            zr += yr*cc + yi*ss; zi += yi*cc - yr*ss;
        }
        float mag = sqrtf(zr*zr + zi*zi + 1e-8f);
        a = mag; hi = mag*g_mask[tid];
    }
    sA[tid] = a; sH[tid] = hi;
    __syncthreads();
    for (int off = 128; off > 0; off >>= 1) {
        if (tid < off) { sA[tid] += sA[tid+off]; sH[tid] += sH[tid+off]; }
        __syncthreads();
    }
    if (tid == 0) g_feat[f*DI+c] = sH[0]/(sA[0]+1e-8f);
}

// ---- loss + softmax ----
__global__ __launch_bounds__(1024)
void loss_alpha_kernel(float* __restrict__ loss_out) {
    __shared__ float rn[32], sFM[DI], red[32];
    int tid = threadIdx.x, wid = tid>>5, lane = tid&31;
    {
        float acc = 0.f;
        for (int c = lane; c < DI; c += 32) { float v = g_feat[wid*DI+c]; acc += v*v; }
        for (int o = 16; o; o >>= 1) acc += __shfl_xor_sync(0xffffffffu, acc, o);
        if (lane == 0) rn[wid] = 1.0f/fmaxf(sqrtf(acc), 1e-12f);
    }
    __syncthreads();
    float gg = 0.f;
    for (int c = tid; c < DI; c += 1024) {
        float gv = 0.f, fm = 0.f;
        for (int f = 0; f < 32; f++) { float v = g_feat[f*DI+c]; gv += v*rn[f]; fm += v; }
        gg += gv*gv; sFM[c] = fm*(1.0f/32.0f);
    }
    for (int o = 16; o; o >>= 1) gg += __shfl_xor_sync(0xffffffffu, gg, o);
    if (lane == 0) red[wid] = gg;
    __syncthreads();
    if (tid == 0) {
        float s = 0.f;
        for (int i = 0; i < 32; i++) s += red[i];
        loss_out[0] = 1.0f - s*(1.0f/1024.0f);
    }
    __syncthreads();
    float mx = -1e30f;
    for (int c = tid; c < DI; c += 1024) mx = fmaxf(mx, sFM[c]);
    for (int o = 16; o; o >>= 1) mx = fmaxf(mx, __shfl_xor_sync(0xffffffffu, mx, o));
    if (lane == 0) red[wid] = mx;
    __syncthreads();
    if (tid == 0) {
        float m = red[0];
        for (int i = 1; i < 32; i++) m = fmaxf(m, red[i]);
        red[0] = m;
    }
    __syncthreads();
    mx = red[0];
    __syncthreads();
    float se = 0.f;
    for (int c = tid; c < DI; c += 1024) { float e = __expf(sFM[c]-mx); sFM[c] = e; se += e; }
    for (int o = 16; o; o >>= 1) se += __shfl_xor_sync(0xffffffffu, se, o);
    if (lane == 0) red[wid] = se;
    __syncthreads();
    if (tid == 0) {
        float s = 0.f;
        for (int i = 0; i < 32; i++) s += red[i];
        red[0] = s;
    }
    __syncthreads();
    float inv = 1.0f/red[0];
    for (int c = tid; c < DI; c += 1024) g_alphaF[c] = sFM[c]*inv;
}

__global__ __launch_bounds__(256)
void att_kernel(const float* __restrict__ A_log) {
    __shared__ float red[256];
    int tid = threadIdx.x;
    if (tid < NS) {
        float mx = -1e30f, mn = 1e30f;
        for (int d = 0; d < DI; d++) {
            float v = A_log[d*NS+tid];
            mx = fmaxf(mx, v); mn = fminf(mn, v);
        }
        g_colmax[tid] = mx; g_colmin[tid] = mn;
    }
    float am = 0.f;
    for (int d = tid; d < DI; d += 256) {
        float s = 0.f;
#pragma unroll
        for (int n = 0; n < NS; n++) { float e = expf(A_log[d*NS+n]); s += e*e; }
        float att = sqrtf(s);
        g_att[d] = att; am = fmaxf(am, att);
    }
    red[tid] = am;
    __syncthreads();
    for (int o = 128; o; o >>= 1) {
        if (tid < o) red[tid] = fmaxf(red[tid], red[tid+o]);
        __syncthreads();
    }
    if (tid == 0) g_attmax[0] = red[0];
}

__global__ void build_A_kernel(const float* __restrict__ A_log) {
    int d = blockIdx.x*blockDim.x + threadIdx.x;
    if (d >= DI) return;
    float alpha = g_alphaF[d]*(1.0f - g_att[d]/(g_attmax[0]+1e-8f));
    alpha = fminf(fmaxf(alpha, 0.0f), 1.0f);
#pragma unroll
    for (int n = 0; n < NS; n++) {
        float al = A_log[d*NS+n];
        float an = (1.0f-alpha)*al + alpha*(g_colmax[n]+g_colmin[n]-al);
        g_A[d*NS+n] = -expf(an);
    }
}

// ---- scan ----
__global__ __launch_bounds__(256)
void scan_kernel(const float* __restrict__ Dp) {
    int tid = blockIdx.x*blockDim.x + threadIdx.x;
    int warp = tid>>5, lane = tid&31;
    int b = warp>>10;
    int d = ((warp&1023)<<1) + (lane>>4);
    int n = lane&15;
    const float An = g_A[d*NS+n];
    const float Dd = Dp[d];
    const float* dl_p = g_delta + ((size_t)(b*DI+d))*LSEQ;
    const float* u_p  = g_xc    + ((size_t)(b*DI+d))*LSEQ;
    const float* z_p  = g_z     + ((size_t)(b*DI+d))*LSEQ;
    const float* bc_p = g_xdbl  + (size_t)b*LSEQ*E2;
    size_t ybase = (size_t)b*LSEQ*DI + d;
    float s = 0.0f;
    for (int t = 0; t < LSEQ; t++) {
        float dl = dl_p[t];
        float u = u_p[t];
        float Bv = bc_p[t*E2+RK+n];
        float Cv = bc_p[t*E2+RK+NS+n];
        s = s*__expf(dl*An) + (dl*u)*Bv;
        float p = s*Cv;
        p += __shfl_xor_sync(0xffffffffu, p, 8);
        p += __shfl_xor_sync(0xffffffffu, p, 4);
        p += __shfl_xor_sync(0xffffffffu, p, 2);
        p += __shfl_xor_sync(0xffffffffu, p, 1);
        if (n == 0) {
            float y = p + u*Dd;
            float z = z_p[t];
            float sg = 1.0f/(1.0f+__expf(-z));
            float yg = y*(z*sg);
            __nv_bfloat16 h, l;
            bsplit(yg, h, l);
            size_t o = ybase + (size_t)t*DI;
            yg_h[o] = h; yg_l[o] = l;
        }
    }
}

// ---- launch ----
extern "C" void kernel_launch(void* const* d_in, const int* in_sizes, int n_in,
                              void* d_out, int out_size) {
    const float* hs  = (const float*)d_in[0];
    const float* ipw = (const float*)d_in[4];
    const float* cw  = (const float*)d_in[5];
    const float* cb  = (const float*)d_in[6];
    const float* xpw = (const float*)d_in[7];
    const float* dtw = (const float*)d_in[8];
    const float* dtb = (const float*)d_in[9];
    const float* alog= (const float*)d_in[10];
    const float* Dp  = (const float*)d_in[11];
    const float* opw = (const float*)d_in[12];
    float* out = (float*)d_out;

    cudaFuncSetAttribute(gemm_mma_kernel<0>, cudaFuncAttributeMaxDynamicSharedMemorySize, GSMEM);
    cudaFuncSetAttribute(gemm_mma_kernel<1>, cudaFuncAttributeMaxDynamicSharedMemorySize, GSMEM);
    cudaFuncSetAttribute(gemm_mma_kernel<2>, cudaFuncAttributeMaxDynamicSharedMemorySize, GSMEM);
    cudaFuncSetAttribute(gemm_mma_kernel<3>, cudaFuncAttributeMaxDynamicSharedMemorySize, GSMEM);

    __nv_bfloat16 *p_hs_h, *p_hs_l, *p_ip_h, *p_ip_l, *p_xp_h, *p_xp_l;
    __nv_bfloat16 *p_dt_h, *p_dt_l, *p_op_h, *p_op_l;
    cudaGetSymbolAddress((void**)&p_hs_h, hs_h);  cudaGetSymbolAddress((void**)&p_hs_l, hs_l);
    cudaGetSymbolAddress((void**)&p_ip_h, w_ip_h); cudaGetSymbolAddress((void**)&p_ip_l, w_ip_l);
    cudaGetSymbolAddress((void**)&p_xp_h, w_xp_h); cudaGetSymbolAddress((void**)&p_xp_l, w_xp_l);
    cudaGetSymbolAddress((void**)&p_dt_h, w_dt_h); cudaGetSymbolAddress((void**)&p_dt_l, w_dt_l);
    cudaGetSymbolAddress((void**)&p_op_h, w_op_h); cudaGetSymbolAddress((void**)&p_op_l, w_op_l);

    init_tables_kernel<<<1, 256>>>();                                                    // 0
    split_kernel<<<(BSZ*LSEQ*DM/4+255)/256, 256>>>(hs,  p_hs_h, p_hs_l, BSZ*LSEQ*DM/4); // 1
    split_kernel<<<(2*DI*DM/4+255)/256, 256>>>(ipw, p_ip_h, p_ip_l, 2*DI*DM/4);         // 2
    gemm_mma_kernel<0><<<dim3(64, 32), 256, GSMEM>>>(nullptr, nullptr);                 // 3 <- profiled
    split_kernel<<<(E2*DI/4+255)/256, 256>>>(xpw, p_xp_h, p_xp_l, E2*DI/4);
    split_kernel<<<(DI*RK/4+255)/256, 256>>>(dtw, p_dt_h, p_dt_l, DI*RK/4);
    split_kernel<<<(DM*DI/4+255)/256, 256>>>(opw, p_op_h, p_op_l, DM*DI/4);

    fft_feat_kernel<<<32*DI, 256>>>();
    loss_alpha_kernel<<<1, 1024>>>(out + OUT_MAIN);
    att_kernel<<<1, 256>>>(alog);
    build_A_kernel<<<DI/256, 256>>>(alog);

    conv_tr_kernel<<<dim3(LSEQ/32, DI/32, BSZ), 256>>>(cw, cb);

    gemm_mma_kernel<1><<<dim3(64, 1), 256, GSMEM>>>(nullptr, nullptr);
    gemm_mma_kernel<2><<<dim3(64, 16), 256, GSMEM>>>(dtb, nullptr);

    scan_kernel<<<(BSZ*DI*NS)/256, 256>>>(Dp);

    gemm_mma_kernel<3><<<dim3(64, 8), 256, GSMEM>>>(nullptr, out);
}

// round 10
// speedup vs baseline: 1.3776x; 1.3776x over previous
#include <cuda_runtime.h>
#include <cuda_bf16.h>
#include <math.h>
#include <stdint.h>

#define BSZ 4
#define LSEQ 2048
#define DM 1024
#define DI 2048
#define NS 16
#define RK 64
#define E2 96
#define OUT_MAIN (BSZ*LSEQ*DM)

__device__ float g_x[(size_t)BSZ*DI*LSEQ];
__device__ float g_z[(size_t)BSZ*DI*LSEQ];
__device__ float g_xc[(size_t)BSZ*DI*LSEQ];
__device__ float g_delta[(size_t)BSZ*DI*LSEQ];
__device__ float g_xdbl[(size_t)BSZ*LSEQ*E2];
__device__ float g_feat[32*DI];
__device__ float g_A[DI*NS];
__device__ float g_alphaF[DI];
__device__ float g_att[DI];
__device__ float g_colmax[NS], g_colmin[NS], g_attmax[1];
__device__ float g_cw[9*16], g_sw[9*16], g_ch[16*16], g_sh[16*16], g_mask[16*9];

__device__ __nv_bfloat16 w_ip_h[(size_t)2*DI*DM], w_ip_l[(size_t)2*DI*DM];
__device__ __nv_bfloat16 w_xp_h[E2*DI], w_xp_l[E2*DI];
__device__ __nv_bfloat16 w_dt_h[DI*RK], w_dt_l[DI*RK];
__device__ __nv_bfloat16 w_op_h[(size_t)DM*DI], w_op_l[(size_t)DM*DI];
__device__ __nv_bfloat16 hs_h[(size_t)BSZ*LSEQ*DM], hs_l[(size_t)BSZ*LSEQ*DM];
__device__ __nv_bfloat16 xcT_h[(size_t)BSZ*LSEQ*DI], xcT_l[(size_t)BSZ*LSEQ*DI];
__device__ __nv_bfloat16 xdbl_h[(size_t)BSZ*LSEQ*E2], xdbl_l[(size_t)BSZ*LSEQ*E2];
__device__ __nv_bfloat16 yg_h[(size_t)BSZ*LSEQ*DI], yg_l[(size_t)BSZ*LSEQ*DI];

__device__ __forceinline__ uint32_t smem_u32(const void* p) {
    uint32_t a;
    asm("{ .reg .u64 t; cvta.to.shared.u64 t, %1; cvt.u32.u64 %0, t; }" : "=r"(a) : "l"(p));
    return a;
}
__device__ __forceinline__ void bsplit(float x, __nv_bfloat16& h, __nv_bfloat16& l) {
    h = __float2bfloat16(x);
    l = __float2bfloat16(x - __bfloat162float(h));
}
#define LDM4(r, addr) \
    asm volatile("ldmatrix.sync.aligned.m8n8.x4.shared.b16 {%0,%1,%2,%3}, [%4];" \
        : "=r"((r)[0]), "=r"((r)[1]), "=r"((r)[2]), "=r"((r)[3]) : "r"(addr))
#define MMA(c, a, b0v, b1v) \
    asm volatile("mma.sync.aligned.m16n8k16.row.col.f32.bf16.bf16.f32 " \
        "{%0,%1,%2,%3}, {%4,%5,%6,%7}, {%8,%9}, {%0,%1,%2,%3};" \
        : "+f"((c)[0]), "+f"((c)[1]), "+f"((c)[2]), "+f"((c)[3]) \
        : "r"((a)[0]), "r"((a)[1]), "r"((a)[2]), "r"((a)[3]), "r"(b0v), "r"(b1v))
#define CP16(s, g) asm volatile("cp.async.cg.shared.global [%0], [%1], 16;" :: "r"(s), "l"(g))
#define CP_COMMIT() asm volatile("cp.async.commit_group;" ::: "memory")
#define CP_WAIT1()  asm volatile("cp.async.wait_group 1;" ::: "memory")

__global__ void init_tables_kernel() {
    int tid = threadIdx.x;
    if (tid < 144) {
        int kw = tid/16, w = tid%16;
        float a = (float)(w*kw)/8.0f;
        g_cw[kw*16+w] = cospif(a); g_sw[kw*16+w] = sinpif(a);
    }
    { int kh = tid/16, h = tid%16;
      float a = (float)(h*kh)/8.0f;
      g_ch[kh*16+h] = cospif(a); g_sh[kh*16+h] = sinpif(a); }
    if (tid < 144) {
        int kh = tid/9, kw = tid%9;
        int i = (kh+8)&15, j = (kw+4)%9;
        float hh = (i-8)/16.0f, ww = (j-4)/9.0f;
        g_mask[tid] = (sqrtf(hh*hh+ww*ww) >= 0.5f) ? 1.0f : 0.0f;
    }
}

__global__ __launch_bounds__(256)
void split_kernel(const float* __restrict__ s, __nv_bfloat16* __restrict__ hp,
                  __nv_bfloat16* __restrict__ lp, int n4) {
    int i = blockIdx.x*256 + threadIdx.x;
    if (i >= n4) return;
    float4 v = *(const float4*)(s + (size_t)i*4);
    __nv_bfloat16 h0,l0,h1,l1,h2,l2,h3,l3;
    bsplit(v.x,h0,l0); bsplit(v.y,h1,l1); bsplit(v.z,h2,l2); bsplit(v.w,h3,l3);
    __nv_bfloat162 hv0 = {h0,h1}, hv1 = {h2,h3}, lv0 = {l0,l1}, lv1 = {l2,l3};
    uint2 hu, lu;
    hu.x = *(uint32_t*)&hv0; hu.y = *(uint32_t*)&hv1;
    lu.x = *(uint32_t*)&lv0; lu.y = *(uint32_t*)&lv1;
    *(uint2*)(hp + (size_t)i*4) = hu;
    *(uint2*)(lp + (size_t)i*4) = lu;
}

// ---- 2-stage cp.async bf16x3 GEMM, occupancy 2 ----
#define STG 40960
#define PL_AH 0
#define PL_AL 10240
#define PL_BH 20480
#define PL_BL 30720
#define GSMEM (2*STG)

template<int MODE>
__global__ __launch_bounds__(256, 2)
void gemm_mma_kernel(const float* __restrict__ bias, float* __restrict__ Out)
{
    extern __shared__ char sm[];
    const __nv_bfloat16 *Wh, *Wl, *Xh, *Xl;
    int ldw, ldx, K, wmax;
    if (MODE==0) { Wh=w_ip_h; Wl=w_ip_l; Xh=hs_h;   Xl=hs_l;   ldw=DM; ldx=DM; K=DM; wmax=2*DI-1; }
    else if (MODE==1) { Wh=w_xp_h; Wl=w_xp_l; Xh=xcT_h; Xl=xcT_l; ldw=DI; ldx=DI; K=DI; wmax=E2-1; }
    else if (MODE==2) { Wh=w_dt_h; Wl=w_dt_l; Xh=xdbl_h; Xl=xdbl_l; ldw=RK; ldx=E2; K=RK; wmax=DI-1; }
    else { Wh=w_op_h; Wl=w_op_l; Xh=yg_h; Xl=yg_l; ldw=DI; ldx=DI; K=DI; wmax=DM-1; }

    int tid = threadIdx.x, wid = tid>>5, lane = tid&31;
    int wm = wid & 1, wn = wid >> 1;
    int i0 = blockIdx.y*128, j0 = blockIdx.x*128;
    uint32_t sb = smem_u32(sm);
    int frow = ((lane>>3)&1)*8 + (lane&7);
    uint32_t khalf = (uint32_t)(lane>>4)*16;
    uint32_t aOff = (uint32_t)(wm*64 + frow)*80 + khalf;
    uint32_t bOff = (uint32_t)(wn*32 + frow)*80 + khalf;

    float acc[4][4][4];
#pragma unroll
    for (int a=0;a<4;a++)
#pragma unroll
        for (int b=0;b<4;b++)
#pragma unroll
            for (int q=0;q<4;q++) acc[a][b][q]=0.f;

    int NC = K/32;

    auto issue = [&](int c) {
        if (c >= NC) return;
        int s = c & 1, k0 = c*32;
        uint32_t base = sb + (uint32_t)s*STG;
#pragma unroll
        for (int it=0; it<2; it++) {
            int idx = tid + it*256;
            int r = idx>>2, u = idx&3;
            uint32_t so = (uint32_t)r*80 + (uint32_t)u*16;
            int wr = i0 + r; if (wr > wmax) wr = wmax;
            size_t wo = (size_t)wr*ldw + k0 + u*8;
            size_t xo = (size_t)(j0+r)*ldx + k0 + u*8;
            CP16(base+PL_AH+so, Wh+wo);
            CP16(base+PL_AL+so, Wl+wo);
            CP16(base+PL_BH+so, Xh+xo);
            CP16(base+PL_BL+so, Xl+xo);
        }
    };

    issue(0); CP_COMMIT();
    issue(1); CP_COMMIT();
    CP_WAIT1();
    __syncthreads();

    for (int c = 0; c < NC; c++) {
        uint32_t st = sb + (uint32_t)(c&1)*STG;
#pragma unroll
        for (int kk = 0; kk < 2; kk++) {
            uint32_t ko = (uint32_t)kk*32;
            uint32_t ah[4][4], al[4][4];
#pragma unroll
            for (int mi=0; mi<4; mi++) {
                LDM4(ah[mi], st+PL_AH+aOff+(uint32_t)mi*1280+ko);
                LDM4(al[mi], st+PL_AL+aOff+(uint32_t)mi*1280+ko);
            }
#pragma unroll
            for (int j=0; j<2; j++) {
                uint32_t bh[4], bl[4];
                LDM4(bh, st+PL_BH+bOff+(uint32_t)j*1280+ko);
                LDM4(bl, st+PL_BL+bOff+(uint32_t)j*1280+ko);
#pragma unroll
                for (int mi=0; mi<4; mi++) {
#pragma unroll
                    for (int nt=0; nt<2; nt++) {
                        float* cc = acc[mi][j*2+nt];
                        MMA(cc, ah[mi], bh[nt], bh[nt+2]);
                        MMA(cc, ah[mi], bl[nt], bl[nt+2]);
                        MMA(cc, al[mi], bh[nt], bh[nt+2]);
                    }
                }
            }
        }
        __syncthreads();
        issue(c+2);
        CP_COMMIT();
        CP_WAIT1();
        __syncthreads();
    }

#pragma unroll
    for (int mi=0; mi<4; mi++) {
        int mBase = i0 + wm*64 + mi*16 + (lane>>2);
#pragma unroll
        for (int ni=0; ni<4; ni++) {
            int n0 = j0 + wn*32 + ni*8 + (lane&3)*2;
            float* c = acc[mi][ni];
#pragma unroll
            for (int rr=0; rr<2; rr++) {
                int m = mBase + rr*8;
                float v0 = c[rr*2], v1 = c[rr*2+1];
                if (MODE==0) {
                    int b_ = n0>>11, l_ = n0&2047;
                    float* dst = (m < DI) ? (g_x + ((size_t)(b_*DI+m))*LSEQ + l_)
                                          : (g_z + ((size_t)(b_*DI+m-DI))*LSEQ + l_);
                    float2 o; o.x=v0; o.y=v1;
                    *(float2*)dst = o;
                } else if (MODE==1) {
                    if (m < RK) {
                        __nv_bfloat16 h0,l0,h1,l1;
                        bsplit(v0,h0,l0); bsplit(v1,h1,l1);
                        xdbl_h[(size_t)n0*E2+m] = h0; xdbl_l[(size_t)n0*E2+m] = l0;
                        xdbl_h[(size_t)(n0+1)*E2+m] = h1; xdbl_l[(size_t)(n0+1)*E2+m] = l1;
                    } else if (m < E2) {
                        g_xdbl[(size_t)n0*E2 + m] = v0;
                        g_xdbl[(size_t)(n0+1)*E2 + m] = v1;
                    }
                } else if (MODE==2) {
                    int b_ = n0>>11, l_ = n0&2047;
                    float bi = bias[m];
                    float s0 = v0 + bi, s1 = v1 + bi;
                    s0 = (s0 > 20.0f) ? s0 : log1pf(__expf(s0));
                    s1 = (s1 > 20.0f) ? s1 : log1pf(__expf(s1));
                    float2 o; o.x=s0; o.y=s1;
                    *(float2*)(g_delta + ((size_t)(b_*DI+m))*LSEQ + l_) = o;
                } else {
                    Out[(size_t)n0*DM + m]     = v0;
                    Out[(size_t)(n0+1)*DM + m] = v1;
                }
            }
        }
    }
}

// ---- fused conv(4)+SiLU + transpose + split ----
__global__ __launch_bounds__(256)
void conv_tr_kernel(const float* __restrict__ cw, const float* __restrict__ cb) {
    __shared__ float tile[32][36];
    __shared__ float t2[32][33];
    __shared__ float cwS[32][4];
    __shared__ float cbS[32];
    int b = blockIdx.z;
    int l0 = blockIdx.x*32, d0 = blockIdx.y*32;
    int tx = threadIdx.x & 31, ty = threadIdx.x >> 5;
    int tid = threadIdx.x;

    if (tid < 128) cwS[tid>>2][tid&3] = cw[(d0 + (tid>>2))*4 + (tid&3)];
    else if (tid < 160) cbS[tid-128] = cb[d0 + tid - 128];
#pragma unroll
    for (int q = 0; q < 5; q++) {
        int idx = tid + q*256;
        if (idx < 32*36) {
            int r = idx / 36, cc = idx % 36;
            int l = l0 - 4 + cc;
            tile[r][cc] = (l >= 0) ? g_x[((size_t)(b*DI + d0 + r))*LSEQ + l] : 0.0f;
        }
    }
    __syncthreads();
#pragma unroll
    for (int j = 0; j < 32; j += 8) {
        int r = ty + j;
        float acc = cbS[r];
#pragma unroll
        for (int k = 0; k < 4; k++) acc = fmaf(tile[r][tx+1+k], cwS[r][k], acc);
        float sg = 1.0f/(1.0f+__expf(-acc));
        float v = acc*sg;
        g_xc[((size_t)(b*DI + d0 + r))*LSEQ + l0 + tx] = v;
        t2[r][tx] = v;
    }
    __syncthreads();
    size_t dbase = (size_t)b*LSEQ*DI;
#pragma unroll
    for (int j = 0; j < 32; j += 8) {
        float v = t2[tx][ty+j];
        __nv_bfloat16 h, l;
        bsplit(v, h, l);
        size_t o = dbase + (size_t)(l0+ty+j)*DI + d0+tx;
        xcT_h[o] = h; xcT_l[o] = l;
    }
}

// ---- fft features: 16 channels per block ----
__global__ __launch_bounds__(256)
void fft_feat_kernel() {
    __shared__ float xt[256][17];
    __shared__ float Yr[144][17], Yi[144][17];
    int bid = blockIdx.x;               // 32 frames * 128 groups
    int f = bid >> 7, c0 = (bid & 127) << 4;
    int b = f >> 3, t = f & 7;
    int tid = threadIdx.x;
    int c  = tid >> 4;                  // channel 0..15
    int ch = tid & 15;                  // sub-worker 0..15

    const float* src = g_x + ((size_t)(b*DI + c0 + c))*LSEQ + t*256;
#pragma unroll
    for (int i = 0; i < 16; i++) {
        int pix = i*16 + ch;
        xt[pix][c] = src[pix];
    }
    __syncthreads();
#pragma unroll
    for (int jj = 0; jj < 9; jj++) {
        int p = jj*16 + ch;
        int h = p/9, kw = p%9;
        float yr = 0.f, yi = 0.f;
#pragma unroll
        for (int w = 0; w < 16; w++) {
            float v = xt[h*16+w][c];
            yr = fmaf(v,  g_cw[kw*16+w], yr);
            yi = fmaf(v, -g_sw[kw*16+w], yi);
        }
        Yr[p][c] = yr; Yi[p][c] = yi;
    }
    __syncthreads();
    float aS = 0.f, hS = 0.f;
#pragma unroll
    for (int jj = 0; jj < 9; jj++) {
        int p = jj*16 + ch;
        int kh = p/9, kw = p%9;
        float zr = 0.f, zi = 0.f;
#pragma unroll
        for (int h = 0; h < 16; h++) {
            float cc = g_ch[kh*16+h], ss = g_sh[kh*16+h];
            float yr = Yr[h*9+kw][c], yi = Yi[h*9+kw][c];
            zr += yr*cc + yi*ss;
            zi += yi*cc - yr*ss;
        }
        float mag = sqrtf(zr*zr + zi*zi + 1e-8f);
        aS += mag; hS += mag * g_mask[p];
    }
#pragma unroll
    for (int o = 8; o; o >>= 1) {
        aS += __shfl_xor_sync(0xffffffffu, aS, o);
        hS += __shfl_xor_sync(0xffffffffu, hS, o);
    }
    if (ch == 0) g_feat[f*DI + c0 + c] = hS / (aS + 1e-8f);
}

// ---- loss + softmax ----
__global__ __launch_bounds__(1024)
void loss_alpha_kernel(float* __restrict__ loss_out) {
    __shared__ float rn[32], sFM[DI], red[32];
    int tid = threadIdx.x, wid = tid>>5, lane = tid&31;
    {
        float acc = 0.f;
        for (int c = lane; c < DI; c += 32) { float v = g_feat[wid*DI+c]; acc += v*v; }
        for (int o = 16; o; o >>= 1) acc += __shfl_xor_sync(0xffffffffu, acc, o);
        if (lane == 0) rn[wid] = 1.0f/fmaxf(sqrtf(acc), 1e-12f);
    }
    __syncthreads();
    float gg = 0.f;
    for (int c = tid; c < DI; c += 1024) {
        float gv = 0.f, fm = 0.f;
        for (int f = 0; f < 32; f++) { float v = g_feat[f*DI+c]; gv += v*rn[f]; fm += v; }
        gg += gv*gv; sFM[c] = fm*(1.0f/32.0f);
    }
    for (int o = 16; o; o >>= 1) gg += __shfl_xor_sync(0xffffffffu, gg, o);
    if (lane == 0) red[wid] = gg;
    __syncthreads();
    if (tid == 0) {
        float s = 0.f;
        for (int i = 0; i < 32; i++) s += red[i];
        loss_out[0] = 1.0f - s*(1.0f/1024.0f);
    }
    __syncthreads();
    float mx = -1e30f;
    for (int c = tid; c < DI; c += 1024) mx = fmaxf(mx, sFM[c]);
    for (int o = 16; o; o >>= 1) mx = fmaxf(mx, __shfl_xor_sync(0xffffffffu, mx, o));
    if (lane == 0) red[wid] = mx;
    __syncthreads();
    if (tid == 0) {
        float m = red[0];
        for (int i = 1; i < 32; i++) m = fmaxf(m, red[i]);
        red[0] = m;
    }
    __syncthreads();
    mx = red[0];
    __syncthreads();
    float se = 0.f;
    for (int c = tid; c < DI; c += 1024) { float e = __expf(sFM[c]-mx); sFM[c] = e; se += e; }
    for (int o = 16; o; o >>= 1) se += __shfl_xor_sync(0xffffffffu, se, o);
    if (lane == 0) red[wid] = se;
    __syncthreads();
    if (tid == 0) {
        float s = 0.f;
        for (int i = 0; i < 32; i++) s += red[i];
        red[0] = s;
    }
    __syncthreads();
    float inv = 1.0f/red[0];
    for (int c = tid; c < DI; c += 1024) g_alphaF[c] = sFM[c]*inv;
}

__global__ __launch_bounds__(256)
void att_kernel(const float* __restrict__ A_log) {
    __shared__ float red[256];
    int tid = threadIdx.x;
    if (tid < NS) {
        float mx = -1e30f, mn = 1e30f;
        for (int d = 0; d < DI; d++) {
            float v = A_log[d*NS+tid];
            mx = fmaxf(mx, v); mn = fminf(mn, v);
        }
        g_colmax[tid] = mx; g_colmin[tid] = mn;
    }
    float am = 0.f;
    for (int d = tid; d < DI; d += 256) {
        float s = 0.f;
#pragma unroll
        for (int n = 0; n < NS; n++) { float e = expf(A_log[d*NS+n]); s += e*e; }
        float att = sqrtf(s);
        g_att[d] = att; am = fmaxf(am, att);
    }
    red[tid] = am;
    __syncthreads();
    for (int o = 128; o; o >>= 1) {
        if (tid < o) red[tid] = fmaxf(red[tid], red[tid+o]);
        __syncthreads();
    }
    if (tid == 0) g_attmax[0] = red[0];
}

__global__ void build_A_kernel(const float* __restrict__ A_log) {
    int d = blockIdx.x*blockDim.x + threadIdx.x;
    if (d >= DI) return;
    float alpha = g_alphaF[d]*(1.0f - g_att[d]/(g_attmax[0]+1e-8f));
    alpha = fminf(fmaxf(alpha, 0.0f), 1.0f);
#pragma unroll
    for (int n = 0; n < NS; n++) {
        float al = A_log[d*NS+n];
        float an = (1.0f-alpha)*al + alpha*(g_colmax[n]+g_colmin[n]-al);
        g_A[d*NS+n] = -expf(an);
    }
}

// ---- scan: block = 16 channels of one batch, B/C staged in smem ----
__global__ __launch_bounds__(256)
void scan_kernel(const float* __restrict__ Dp) {
    __shared__ float bcS[64][32];
    int b = blockIdx.y;
    int d0 = blockIdx.x*16;
    int tid = threadIdx.x, wid = tid>>5, lane = tid&31;
    int d = d0 + (wid<<1) + (lane>>4);
    int n = lane&15;

    const float An = g_A[d*NS+n];
    const float Dd = Dp[d];
    const float* dl_p = g_delta + ((size_t)(b*DI+d))*LSEQ;
    const float* u_p  = g_xc    + ((size_t)(b*DI+d))*LSEQ;
    const float* z_p  = g_z     + ((size_t)(b*DI+d))*LSEQ;
    const float* bc_p = g_xdbl  + (size_t)b*LSEQ*E2 + 64;
    size_t ybase = (size_t)b*LSEQ*DI + d;

    float s = 0.0f;
    for (int t0 = 0; t0 < LSEQ; t0 += 64) {
        __syncthreads();
#pragma unroll
        for (int q = 0; q < 8; q++) {
            int idx = tid + q*256;
            int row = idx >> 5, col = idx & 31;
            bcS[row][col] = bc_p[(size_t)(t0+row)*E2 + col];
        }
        __syncthreads();
        for (int tt = 0; tt < 64; tt += 4) {
            int t = t0 + tt;
            float4 dl4 = *(const float4*)(dl_p + t);
            float4 u4  = *(const float4*)(u_p + t);
            float4 z4  = *(const float4*)(z_p + t);
            float dls[4] = {dl4.x, dl4.y, dl4.z, dl4.w};
            float us[4]  = {u4.x, u4.y, u4.z, u4.w};
            float zs[4]  = {z4.x, z4.y, z4.z, z4.w};
#pragma unroll
            for (int q = 0; q < 4; q++) {
                float dl = dls[q], u = us[q];
                float Bv = bcS[tt+q][n];
                float Cv = bcS[tt+q][16+n];
                s = s*__expf(dl*An) + (dl*u)*Bv;
                float p = s*Cv;
                p += __shfl_xor_sync(0xffffffffu, p, 8);
                p += __shfl_xor_sync(0xffffffffu, p, 4);
                p += __shfl_xor_sync(0xffffffffu, p, 2);
                p += __shfl_xor_sync(0xffffffffu, p, 1);
                if (n == 0) {
                    float y = p + u*Dd;
                    float z = zs[q];
                    float sg = 1.0f/(1.0f+__expf(-z));
                    float yg = y*(z*sg);
                    __nv_bfloat16 h, l;
                    bsplit(yg, h, l);
                    size_t o = ybase + (size_t)(t+q)*DI;
                    yg_h[o] = h; yg_l[o] = l;
                }
            }
        }
    }
}

// ---- launch ----
extern "C" void kernel_launch(void* const* d_in, const int* in_sizes, int n_in,
                              void* d_out, int out_size) {
    const float* hs  = (const float*)d_in[0];
    const float* ipw = (const float*)d_in[4];
    const float* cw  = (const float*)d_in[5];
    const float* cb  = (const float*)d_in[6];
    const float* xpw = (const float*)d_in[7];
    const float* dtw = (const float*)d_in[8];
    const float* dtb = (const float*)d_in[9];
    const float* alog= (const float*)d_in[10];
    const float* Dp  = (const float*)d_in[11];
    const float* opw = (const float*)d_in[12];
    float* out = (float*)d_out;

    cudaFuncSetAttribute(gemm_mma_kernel<0>, cudaFuncAttributeMaxDynamicSharedMemorySize, GSMEM);
    cudaFuncSetAttribute(gemm_mma_kernel<1>, cudaFuncAttributeMaxDynamicSharedMemorySize, GSMEM);
    cudaFuncSetAttribute(gemm_mma_kernel<2>, cudaFuncAttributeMaxDynamicSharedMemorySize, GSMEM);
    cudaFuncSetAttribute(gemm_mma_kernel<3>, cudaFuncAttributeMaxDynamicSharedMemorySize, GSMEM);

    __nv_bfloat16 *p_hs_h, *p_hs_l, *p_ip_h, *p_ip_l, *p_xp_h, *p_xp_l;
    __nv_bfloat16 *p_dt_h, *p_dt_l, *p_op_h, *p_op_l;
    cudaGetSymbolAddress((void**)&p_hs_h, hs_h);  cudaGetSymbolAddress((void**)&p_hs_l, hs_l);
    cudaGetSymbolAddress((void**)&p_ip_h, w_ip_h); cudaGetSymbolAddress((void**)&p_ip_l, w_ip_l);
    cudaGetSymbolAddress((void**)&p_xp_h, w_xp_h); cudaGetSymbolAddress((void**)&p_xp_l, w_xp_l);
    cudaGetSymbolAddress((void**)&p_dt_h, w_dt_h); cudaGetSymbolAddress((void**)&p_dt_l, w_dt_l);
    cudaGetSymbolAddress((void**)&p_op_h, w_op_h); cudaGetSymbolAddress((void**)&p_op_l, w_op_l);

    init_tables_kernel<<<1, 256>>>();                                                    // 0
    split_kernel<<<(BSZ*LSEQ*DM/4+255)/256, 256>>>(hs,  p_hs_h, p_hs_l, BSZ*LSEQ*DM/4); // 1
    split_kernel<<<(2*DI*DM/4+255)/256, 256>>>(ipw, p_ip_h, p_ip_l, 2*DI*DM/4);         // 2
    gemm_mma_kernel<0><<<dim3(64, 32), 256, GSMEM>>>(nullptr, nullptr);                 // 3 <- profiled
    split_kernel<<<(E2*DI/4+255)/256, 256>>>(xpw, p_xp_h, p_xp_l, E2*DI/4);
    split_kernel<<<(DI*RK/4+255)/256, 256>>>(dtw, p_dt_h, p_dt_l, DI*RK/4);
    split_kernel<<<(DM*DI/4+255)/256, 256>>>(opw, p_op_h, p_op_l, DM*DI/4);

    fft_feat_kernel<<<32*128, 256>>>();
    loss_alpha_kernel<<<1, 1024>>>(out + OUT_MAIN);
    att_kernel<<<1, 256>>>(alog);
    build_A_kernel<<<DI/256, 256>>>(alog);

    conv_tr_kernel<<<dim3(LSEQ/32, DI/32, BSZ), 256>>>(cw, cb);

    gemm_mma_kernel<1><<<dim3(64, 1), 256, GSMEM>>>(nullptr, nullptr);
    gemm_mma_kernel<2><<<dim3(64, 16), 256, GSMEM>>>(dtb, nullptr);

    scan_kernel<<<dim3(DI/16, BSZ), 256>>>(Dp);

    gemm_mma_kernel<3><<<dim3(64, 8), 256, GSMEM>>>(nullptr, out);
}